// round 16
// baseline (speedup 1.0000x reference)
#include <cuda_runtime.h>
#include <cstdint>

// ComplexUpSampling2D (resolved interface):
//   inputs : x_re, x_im fp32 [16,128,128,64] (64 MiB each; x_im unused)
//   output : float32 [16,256,256,64] = 67,108,864 elems (268 MiB)
//            = real part of nearest 2x2 complex upsample
//   out[b,oi,oj,c] = x_re[b, oi/2, oj/2, c]
//
// R16: back to the WINNING input-centric mapping (R14: read once, replicate
// in registers — R15's output-centric re-reads regressed). Two deltas:
//   * __stcs evict-first streaming stores: 268MB of write-once lines stop
//     thrashing L2 / stealing LTS capacity from the write drain; input
//     (64 MiB) stays L2-resident across graph replays.
//   * 2 float4 per thread (8 channels): MLP=2 on loads, and each warp store
//     instruction covers denser contiguous runs. Half the threads, same
//     bytes, fewer index computations per byte.

static constexpr long long NEXP  = 16LL * 128 * 128 * 64;  // input floats = 16,777,216
static constexpr long long OUT_F = 4 * NEXP;               // output floats = 67,108,864

// One thread = 8 channels (two adjacent float4) of one input pixel.
//   2x LDG.128 -> 8x STG.128 (4 output sites x 2 consecutive f4).
__global__ void __launch_bounds__(256)
up2x_real_f4x2(const float4* __restrict__ re, float4* __restrict__ out,
               unsigned n_pairs, unsigned cap_f4)
{
    unsigned tid = blockIdx.x * blockDim.x + threadIdx.x;
    if (tid >= n_pairs) return;

    // tid = hb*1024 + w*8 + p   (p = which f4-pair within C: 0..7)
    unsigned p  = tid & 7u;
    unsigned w  = (tid >> 3) & 127u;
    unsigned hb = tid >> 10;              // b*128 + h

    unsigned in_idx = (tid << 1);         // two consecutive f4 of the input
    float4 v0 = __ldg(re + in_idx);
    float4 v1 = __ldg(re + in_idx + 1);

    // output row = 2*hb ; f4 offset = (row*256 + oj)*16 + 2*p
    unsigned base = ((2u * hb) * 256u + 2u * w) * 16u + 2u * p;
    const unsigned ROW = 256u * 16u;      // 4096 f4 per output row

    unsigned idx;
    idx = base;             if (idx + 1u < cap_f4) { __stcs(out + idx, v0); __stcs(out + idx + 1u, v1); }
    idx = base + 16u;       if (idx + 1u < cap_f4) { __stcs(out + idx, v0); __stcs(out + idx + 1u, v1); }
    idx = base + ROW;       if (idx + 1u < cap_f4) { __stcs(out + idx, v0); __stcs(out + idx + 1u, v1); }
    idx = base + ROW + 16u; if (idx + 1u < cap_f4) { __stcs(out + idx, v0); __stcs(out + idx + 1u, v1); }
}

// Scalar alignment fallback (proven in R14 lineage).
__global__ void __launch_bounds__(256)
up2x_real_scalar(const float* __restrict__ re, float* __restrict__ out,
                 long long n_elems, long long cap_f)
{
    long long e = blockIdx.x * (long long)blockDim.x + threadIdx.x;
    if (e >= n_elems) return;

    unsigned c  = (unsigned)(e & 63);
    unsigned w  = (unsigned)((e >> 6) & 127);
    unsigned hb = (unsigned)(e >> 13);

    float v = __ldg(re + e);
    long long base = ((2LL * hb) * 256 + 2 * w) * 64 + c;
    const long long ROW = 256 * 64;

    long long s;
    s = base;            if (s < cap_f) out[s] = v;
    s = base + 64;       if (s < cap_f) out[s] = v;
    s = base + ROW;      if (s < cap_f) out[s] = v;
    s = base + ROW + 64; if (s < cap_f) out[s] = v;
}

extern "C" void kernel_launch(void* const* d_in, const int* in_sizes, int n_in,
                              void* d_out, int out_size)
{
    // Locate x_re by size (element- or byte-count), not position.
    int ire = -1;
    for (int i = 0; i < n_in; i++) {
        long long s = in_sizes[i];
        if (s == NEXP || s == NEXP * 4) { ire = i; break; }
    }
    if (ire < 0) ire = 0;

    const float* re_p = (const float*)d_in[ire];
    float* out_p = (float*)d_out;

    // Read extent: at most NEXP floats.
    long long s_re = in_sizes[ire];
    long long n_elems = (s_re >= NEXP) ? NEXP : s_re;

    // Write cap in floats: min(out_size, OUT_F) — safe under element- or
    // byte-count readings of out_size.
    long long cap_f = (long long)out_size;
    if (cap_f < 0) cap_f = 0;
    if (cap_f > OUT_F) cap_f = OUT_F;

    bool aligned =
        ((((uintptr_t)re_p) | ((uintptr_t)out_p)) & 15) == 0 &&
        (n_elems % 8 == 0) && (cap_f % 4 == 0);

    const int block = 256;

    if (aligned) {
        unsigned n_pairs = (unsigned)(n_elems / 8);            // 2,097,152
        unsigned cap_f4  = (unsigned)(cap_f / 4);              // 16,777,216
        int grid = (int)((n_pairs + block - 1) / block);       // 8192
        if (grid > 0)
            up2x_real_f4x2<<<grid, block>>>((const float4*)re_p, (float4*)out_p,
                                            n_pairs, cap_f4);
    } else {
        long long grid_ll = (n_elems + block - 1) / block;
        if (grid_ll > 0)
            up2x_real_scalar<<<(int)grid_ll, block>>>(re_p, out_p, n_elems, cap_f);
    }
}

// round 17
// speedup vs baseline: 1.2583x; 1.2583x over previous
#include <cuda_runtime.h>
#include <cstdint>

// ComplexUpSampling2D (resolved interface):
//   inputs : x_re, x_im fp32 [16,128,128,64] (64 MiB each; x_im unused)
//   output : float32 [16,256,256,64] = 67,108,864 elems (268 MiB)
//            = real part of nearest 2x2 complex upsample
//   out[b,oi,oj,c] = x_re[b, oi/2, oj/2, c]
//
// R17: exact R14 structure (the 49.1us/DRAM-71% winner: one thread = one
// input float4, read once, replicate to 4 sites in registers, per-warp
// stores = contiguous 256B runs with every 32B sector completed by a single
// wavefront). ONE delta: __stcs evict-first streaming stores (+__ldg reads)
// so 268MB of write-once lines stop allocating in L2 / evicting the
// L2-resident input. Single-variable experiment vs R14.

static constexpr long long NEXP  = 16LL * 128 * 128 * 64;  // input floats = 16,777,216
static constexpr long long OUT_F = 4 * NEXP;               // output floats = 67,108,864

// One thread = one float4 of x_re (4 channels of one input pixel)
//   1x LDG.128 -> 4x STG.128 (2 rows x 2 cols), evict-first.
__global__ void __launch_bounds__(256)
up2x_real_f4(const float4* __restrict__ re, float4* __restrict__ out,
             unsigned n_f4_in, unsigned cap_f4)
{
    unsigned tid = blockIdx.x * blockDim.x + threadIdx.x;
    if (tid >= n_f4_in) return;

    unsigned c4 = tid & 15u;          // float4 group within C=64
    unsigned w  = (tid >> 4) & 127u;  // input column
    unsigned hb = tid >> 11;          // b*128 + h  (output row = 2*hb)

    float4 v = __ldg(re + tid);

    unsigned base = ((2u * hb) * 256u + 2u * w) * 16u + c4;
    const unsigned ROW = 256u * 16u;  // 4096 f4 per output row

    unsigned idx;
    idx = base;             if (idx < cap_f4) __stcs(out + idx, v);   // (oi,   oj  )
    idx = base + 16u;       if (idx < cap_f4) __stcs(out + idx, v);   // (oi,   oj+1)
    idx = base + ROW;       if (idx < cap_f4) __stcs(out + idx, v);   // (oi+1, oj  )
    idx = base + ROW + 16u; if (idx < cap_f4) __stcs(out + idx, v);   // (oi+1, oj+1)
}

// Scalar alignment fallback.
__global__ void __launch_bounds__(256)
up2x_real_scalar(const float* __restrict__ re, float* __restrict__ out,
                 long long n_elems, long long cap_f)
{
    long long e = blockIdx.x * (long long)blockDim.x + threadIdx.x;
    if (e >= n_elems) return;

    unsigned c  = (unsigned)(e & 63);
    unsigned w  = (unsigned)((e >> 6) & 127);
    unsigned hb = (unsigned)(e >> 13);

    float v = __ldg(re + e);
    long long base = ((2LL * hb) * 256 + 2 * w) * 64 + c;
    const long long ROW = 256 * 64;

    long long s;
    s = base;            if (s < cap_f) out[s] = v;
    s = base + 64;       if (s < cap_f) out[s] = v;
    s = base + ROW;      if (s < cap_f) out[s] = v;
    s = base + ROW + 64; if (s < cap_f) out[s] = v;
}

extern "C" void kernel_launch(void* const* d_in, const int* in_sizes, int n_in,
                              void* d_out, int out_size)
{
    // Locate x_re by size (element- or byte-count), not position.
    int ire = -1;
    for (int i = 0; i < n_in; i++) {
        long long s = in_sizes[i];
        if (s == NEXP || s == NEXP * 4) { ire = i; break; }
    }
    if (ire < 0) ire = 0;

    const float* re_p = (const float*)d_in[ire];
    float* out_p = (float*)d_out;

    // Read extent: at most NEXP floats.
    long long s_re = in_sizes[ire];
    long long n_elems = (s_re >= NEXP) ? NEXP : s_re;

    // Write cap in floats: min(out_size, OUT_F) — safe under element- or
    // byte-count readings of out_size.
    long long cap_f = (long long)out_size;
    if (cap_f < 0) cap_f = 0;
    if (cap_f > OUT_F) cap_f = OUT_F;

    bool aligned =
        ((((uintptr_t)re_p) | ((uintptr_t)out_p)) & 15) == 0 &&
        (n_elems % 4 == 0) && (cap_f % 4 == 0);

    const int block = 256;

    if (aligned) {
        unsigned n_f4_in = (unsigned)(n_elems / 4);            // 4,194,304
        unsigned cap_f4  = (unsigned)(cap_f / 4);              // 16,777,216
        int grid = (int)((n_f4_in + block - 1) / block);       // 16384
        if (grid > 0)
            up2x_real_f4<<<grid, block>>>((const float4*)re_p, (float4*)out_p,
                                          n_f4_in, cap_f4);
    } else {
        long long grid_ll = (n_elems + block - 1) / block;
        if (grid_ll > 0)
            up2x_real_scalar<<<(int)grid_ll, block>>>(re_p, out_p, n_elems, cap_f);
    }
}